// round 11
// baseline (speedup 1.0000x reference)
#include <cuda_runtime.h>
#include <cuda_fp16.h>
#include <cstdint>

#define NH 16
#define SEQ 2048
#define HD 64
#define BM 128
#define BN 64
#define NT (SEQ / BN)    // 32

#define PU 36
#define PF 72

// ---- SMEM layout (bytes) ----
#define TILE_B (64 * 144)                 // 9216
#define BUF_B (3 * TILE_B)                // 27648
#define SK1_B(b) ((b) * BUF_B)
#define SRED_B (2 * BUF_B)                // 55296
#define SLAM_B (SRED_B + 32)
#define SMEM_BYTES (SLAM_B + 32)

// ---- global scratch: per (head, tile) packed fp16 image, 192 rows x 128B ----
#define SCRT_B (192 * 128)                // 24576: [K1 64r | K2 64r | VT 64r]
__device__ uint8_t g_scr[NH * NT * SCRT_B];

__device__ float g_psum[NH * 16];
__device__ float g_psq[NH * 16];
__device__ float g_mean[NH];
__device__ float g_istd[NH];
__device__ int g_cnt[NH];

__device__ __forceinline__ float ex2(float x) {
    float r; asm("ex2.approx.ftz.f32 %0, %1;" : "=f"(r) : "f"(x)); return r;
}
__device__ __forceinline__ uint32_t pack2(float lo, float hi) {
    uint32_t r;
    asm("cvt.rn.f16x2.f32 %0, %1, %2;" : "=r"(r) : "f"(hi), "f"(lo));
    return r;
}
__device__ __forceinline__ uint32_t smem_u32(const void* p) {
    uint32_t a;
    asm("{ .reg .u64 t; cvta.to.shared.u64 t, %1; cvt.u32.u64 %0, t; }" : "=r"(a) : "l"(p));
    return a;
}
__device__ __forceinline__ void mma16(float d[4], const uint32_t a[4], const uint32_t b[2]) {
    asm volatile(
        "mma.sync.aligned.m16n8k16.row.col.f32.f16.f16.f32 "
        "{%0,%1,%2,%3},{%4,%5,%6,%7},{%8,%9},{%0,%1,%2,%3};"
        : "+f"(d[0]), "+f"(d[1]), "+f"(d[2]), "+f"(d[3])
        : "r"(a[0]), "r"(a[1]), "r"(a[2]), "r"(a[3]), "r"(b[0]), "r"(b[1]));
}
__device__ __forceinline__ void ldsm_x4(uint32_t b[4], uint32_t addr) {
    asm volatile("ldmatrix.sync.aligned.m8n8.x4.shared.b16 {%0,%1,%2,%3}, [%4];"
                 : "=r"(b[0]), "=r"(b[1]), "=r"(b[2]), "=r"(b[3]) : "r"(addr));
}
#define CP_ASYNC16(dst, src) \
    asm volatile("cp.async.cg.shared.global [%0], [%1], 16;" :: "r"(dst), "l"(src) : "memory")
#define CP_COMMIT() asm volatile("cp.async.commit_group;" ::: "memory")
#define CP_WAIT0()  asm volatile("cp.async.wait_group 0;" ::: "memory")

// ---------------------------------------------------------------------------
// Prepass: convert K (both halves) and V (transposed via smem) to fp16 images.
// ---------------------------------------------------------------------------
__global__ void __launch_bounds__(256) conv_kernel(const float* __restrict__ k,
                                                   const float* __restrict__ v) {
    __shared__ float sv[64 * 65];
    const int t = blockIdx.x;
    const int h = blockIdx.y;
    const int tid = threadIdx.x;
    const int kbase = t * BN;
    const float* kh = k + (size_t)h * SEQ * 2 * HD;
    const float* vh = v + (size_t)h * SEQ * HD;
    uint8_t* dst = g_scr + (size_t)(h * NT + t) * SCRT_B;

    // K halves: coalesced, thread handles 8 consecutive fp32 -> one 16B store
#pragma unroll
    for (int i = 0; i < 4; i++) {
        int e = tid + i * 256;          // 0..1023
        int r = e >> 4;                 // 0..63
        int c8 = e & 15;                // 8-col group
        const float* src = kh + (size_t)(kbase + r) * 2 * HD + c8 * 8;
        float4 a = *(const float4*)(src);
        float4 b = *(const float4*)(src + 4);
        int off = ((c8 < 8) ? 0 : 8192) + r * 128 + (c8 & 7) * 16;
        uint4 pk = {pack2(a.x, a.y), pack2(a.z, a.w), pack2(b.x, b.y), pack2(b.z, b.w)};
        *(uint4*)(dst + off) = pk;
    }
    // V: coalesced load into smem (fp32)
#pragma unroll
    for (int i = 0; i < 4; i++) {
        int e = tid + i * 256;          // 0..1023
        int r = e >> 4;
        int c4 = e & 15;
        float4 val = *(const float4*)(vh + (size_t)(kbase + r) * HD + c4 * 4);
        float* d = sv + r * 65 + c4 * 4;
        d[0] = val.x; d[1] = val.y; d[2] = val.z; d[3] = val.w;
    }
    __syncthreads();
    // transpose write: output row = dim d, cols = keys; 16B chunks, coalesced
#pragma unroll
    for (int i = 0; i < 2; i++) {
        int e = tid + i * 256;          // 0..511
        int d = e >> 3;                 // 0..63
        int k0 = (e & 7) * 8;
        uint4 pk;
        pk.x = pack2(sv[(k0 + 0) * 65 + d], sv[(k0 + 1) * 65 + d]);
        pk.y = pack2(sv[(k0 + 2) * 65 + d], sv[(k0 + 3) * 65 + d]);
        pk.z = pack2(sv[(k0 + 4) * 65 + d], sv[(k0 + 5) * 65 + d]);
        pk.w = pack2(sv[(k0 + 6) * 65 + d], sv[(k0 + 7) * 65 + d]);
        *(uint4*)(dst + 16384 + d * 128 + k0 * 2) = pk;
    }
}

// ---------------------------------------------------------------------------
__global__ void __launch_bounds__(256, 2) attn_kernel(
    const float* __restrict__ q, float* __restrict__ out,
    const float* __restrict__ lq1, const float* __restrict__ lq2,
    const float* __restrict__ lk1, const float* __restrict__ lk2) {
    extern __shared__ char smc[];
    uint32_t* smu = (uint32_t*)smc;
    float* smf = (float*)smc;
    const uint32_t sb = smem_u32(smc);

    const int tid = threadIdx.x;
    const int w = tid >> 5;
    const int lane = tid & 31;
    const int lq = lane >> 2;
    const int lt = lane & 3;
    const int half2w = (w >= 4);
    const int wrow = (w & 3) * 32;
    const int h = blockIdx.y;
    const int qbase = blockIdx.x * BM;

    const float C = 0.18033688011112042f;  // (1/8)*log2(e)

    const float* qh = q + (size_t)h * SEQ * 2 * HD;
    const uint8_t* scr = g_scr + (size_t)h * NT * SCRT_B;

    // x4 ldmatrix per-lane offsets:
    //   QK: lane-group bit selects kg2 pair member (+32B)
    //   PV: lane-group bit selects n-tile pair member (+1152B = next n row-block)
    const uint32_t lmQK = (uint32_t)((lane & 7) * 144 + ((lane >> 3) & 1) * 16 + ((lane >> 4) & 1) * 32);
    const uint32_t lmPV = (uint32_t)((lane & 7) * 144 + ((lane >> 3) & 1) * 16 + ((lane >> 4) & 1) * 1152);

    // ---- warp 0: lambda into smem (read back only AFTER the mainloop) ----
    if (w == 0) {
        float a = lq1[lane] * lk1[lane] + lq1[lane + 32] * lk1[lane + 32];
        float b = lq2[lane] * lk2[lane] + lq2[lane + 32] * lk2[lane + 32];
#pragma unroll
        for (int o = 16; o > 0; o >>= 1) {
            a += __shfl_xor_sync(0xffffffffu, a, o);
            b += __shfl_xor_sync(0xffffffffu, b, o);
        }
        if (lane == 0) smf[SLAM_B >> 2] = __expf(a) - __expf(b) + 0.8f;
    }

    // ---- stage Q (fp16, scaled): Q1 at byte 0, Q2 at byte BUF_B ----
    for (int e = tid; e < BM * 32; e += 256) {
        int c4 = e & 31;
        int r = e >> 5;
        float4 val = *(const float4*)(qh + (size_t)(qbase + r) * 2 * HD + c4 * 4);
        int baseu = ((c4 < 16) ? 0 : BUF_B) >> 2;
        int d0 = (c4 & 15) * 4;
        uint2 pk = {pack2(val.x * C, val.y * C), pack2(val.z * C, val.w * C)};
        *(uint2*)(smu + baseu + r * PU + (d0 >> 1)) = pk;
    }
    __syncthreads();

    // ---- extract Q fragments ----
    uint32_t qa[2][4][4];
    {
        const uint32_t* sq = smu + ((half2w ? BUF_B : 0) >> 2);
#pragma unroll
        for (int m = 0; m < 2; m++)
#pragma unroll
            for (int kg = 0; kg < 4; kg++) {
                int r0 = wrow + m * 16 + lq;
                int c0 = kg * 8 + lt;
                qa[m][kg][0] = sq[r0 * PU + c0];
                qa[m][kg][1] = sq[(r0 + 8) * PU + c0];
                qa[m][kg][2] = sq[r0 * PU + c0 + 4];
                qa[m][kg][3] = sq[(r0 + 8) * PU + c0 + 4];
            }
    }
    __syncthreads();

    // ---- prologue: async-stage tile 0 into buffer 0 ----
#pragma unroll
    for (int i = 0; i < 6; i++) {
        int c = tid + i * 256;
        uint32_t dst = sb + SK1_B(0) + (c >> 3) * 144 + (c & 7) * 16;
        CP_ASYNC16(dst, scr + c * 16);
    }
    CP_COMMIT();

    float o[2][8][4] = {};
    float lrow[4] = {};

    for (int t = 0; t < NT; t++) {
        CP_WAIT0();
        __syncthreads();

        const int buf = t & 1;
        if (t + 1 < NT) {
            const uint8_t* src = scr + (size_t)(t + 1) * SCRT_B;
            const uint32_t db = sb + SK1_B(buf ^ 1);
#pragma unroll
            for (int i = 0; i < 6; i++) {
                int c = tid + i * 256;
                CP_ASYNC16(db + (c >> 3) * 144 + (c & 7) * 16, src + c * 16);
            }
        }
        CP_COMMIT();

        const uint32_t skA = sb + SK1_B(buf) + (half2w ? TILE_B : 0) + lmQK;
        const uint32_t svA = sb + SK1_B(buf) + 2 * TILE_B + lmPV;

        // ---- per k-group: QK (two n-tiles) -> softmax -> P in regs -> PV ----
#pragma unroll
        for (int kg = 0; kg < 4; kg++) {
            uint32_t pa[2][4];
#pragma unroll
            for (int p = 0; p < 2; p++) {
                const int n = kg * 2 + p;
                float s[2][4] = {};
#pragma unroll
                for (int j = 0; j < 2; j++) {
                    uint32_t b4[4];
                    ldsm_x4(b4, skA + n * 1152 + j * 64);
                    mma16(s[0], qa[0][2 * j], b4);
                    mma16(s[1], qa[1][2 * j], b4);
                    mma16(s[0], qa[0][2 * j + 1], b4 + 2);
                    mma16(s[1], qa[1][2 * j + 1], b4 + 2);
                }
#pragma unroll
                for (int m = 0; m < 2; m++) {
                    float p0 = ex2(s[m][0]), p1 = ex2(s[m][1]);
                    float p2 = ex2(s[m][2]), p3 = ex2(s[m][3]);
                    lrow[m * 2 + 0] += p0 + p1;
                    lrow[m * 2 + 1] += p2 + p3;
                    pa[m][p * 2 + 0] = pack2(p0, p1);
                    pa[m][p * 2 + 1] = pack2(p2, p3);
                }
            }
#pragma unroll
            for (int n2 = 0; n2 < 4; n2++) {
                uint32_t b4[4];
                ldsm_x4(b4, svA + n2 * 2304 + kg * 32);
                mma16(o[0][2 * n2], pa[0], b4);
                mma16(o[1][2 * n2], pa[1], b4);
                mma16(o[0][2 * n2 + 1], pa[0], b4 + 2);
                mma16(o[1][2 * n2 + 1], pa[1], b4 + 2);
            }
        }
    }

    // ---- quad-reduce softmax denominators ----
#pragma unroll
    for (int i = 0; i < 4; i++) {
        lrow[i] += __shfl_xor_sync(0xffffffffu, lrow[i], 1);
        lrow[i] += __shfl_xor_sync(0xffffffffu, lrow[i], 2);
    }

    const float lam = smf[SLAM_B >> 2];
    __syncthreads();

    float* exg = smf;
    if (half2w) {
#pragma unroll
        for (int m = 0; m < 2; m++) {
            float s0 = lam / lrow[m * 2 + 0];
            float s1 = lam / lrow[m * 2 + 1];
            int r0 = wrow + m * 16 + lq;
#pragma unroll
            for (int n = 0; n < 8; n++) {
                float* pp = exg + r0 * PF + n * 8 + lt * 2;
                pp[0] = o[m][n][0] * s0;
                pp[1] = o[m][n][1] * s0;
                pp[8 * PF] = o[m][n][2] * s1;
                pp[8 * PF + 1] = o[m][n][3] * s1;
            }
        }
    }
    __syncthreads();

    if (!half2w) {
        float lsum = 0.f, lsq = 0.f;
#pragma unroll
        for (int m = 0; m < 2; m++) {
            float r0s = 1.f / lrow[m * 2 + 0];
            float r1s = 1.f / lrow[m * 2 + 1];
            int r0 = wrow + m * 16 + lq;
            float* orow0 = out + ((size_t)h * SEQ + qbase + r0) * HD;
            float* orow1 = out + ((size_t)h * SEQ + qbase + r0 + 8) * HD;
#pragma unroll
            for (int n = 0; n < 8; n++) {
                const float* pp = exg + r0 * PF + n * 8 + lt * 2;
                float v0 = o[m][n][0] * r0s - pp[0];
                float v1 = o[m][n][1] * r0s - pp[1];
                float v2 = o[m][n][2] * r1s - pp[8 * PF];
                float v3 = o[m][n][3] * r1s - pp[8 * PF + 1];
                int c = n * 8 + lt * 2;
                float2 t0 = {v0, v1};
                float2 t1 = {v2, v3};
                *(float2*)(orow0 + c) = t0;
                *(float2*)(orow1 + c) = t1;
                lsum += v0 + v1 + v2 + v3;
                lsq += v0 * v0 + v1 * v1 + v2 * v2 + v3 * v3;
            }
        }
#pragma unroll
        for (int off = 16; off > 0; off >>= 1) {
            lsum += __shfl_xor_sync(0xffffffffu, lsum, off);
            lsq += __shfl_xor_sync(0xffffffffu, lsq, off);
        }
        if (lane == 0) { smf[(SRED_B >> 2) + w] = lsum; smf[(SRED_B >> 2) + 4 + w] = lsq; }
    }
    __syncthreads();
    if (tid == 0) {
        const float* rd = smf + (SRED_B >> 2);
        g_psum[h * 16 + blockIdx.x] = rd[0] + rd[1] + rd[2] + rd[3];
        g_psq[h * 16 + blockIdx.x] = rd[4] + rd[5] + rd[6] + rd[7];
        __threadfence();
        int c = atomicAdd(&g_cnt[h], 1);
        if (c == 15) {
            float s = 0.f, qq = 0.f;
#pragma unroll
            for (int i = 0; i < 16; i++) { s += g_psum[h * 16 + i]; qq += g_psq[h * 16 + i]; }
            const float inv_n = 1.0f / (float)(SEQ * HD);
            float mean = s * inv_n;
            float var = qq * inv_n - mean * mean;
            g_mean[h] = mean;
            g_istd[h] = rsqrtf(var + 1e-5f);
            g_cnt[h] = 0;
        }
    }
}

// ---------------------------------------------------------------------------
__global__ void norm_kernel(float* __restrict__ out, const float* __restrict__ gamma,
                            const float* __restrict__ beta) {
    int base = (blockIdx.x * blockDim.x + threadIdx.x) * 8;
    int h = base >> 17;
    float mean = g_mean[h];
    float is = g_istd[h];
#pragma unroll
    for (int half = 0; half < 2; half++) {
        int idx = base + half * 4;
        int d = idx & (HD - 1);
        float4 x = *(float4*)(out + idx);
        float4 g = *(const float4*)(gamma + h * HD + d);
        float4 b = *(const float4*)(beta + h * HD + d);
        x.x = ((x.x - mean) * is * g.x + b.x) * 0.2f;
        x.y = ((x.y - mean) * is * g.y + b.y) * 0.2f;
        x.z = ((x.z - mean) * is * g.z + b.z) * 0.2f;
        x.w = ((x.w - mean) * is * g.w + b.w) * 0.2f;
        *(float4*)(out + idx) = x;
    }
}

// ---------------------------------------------------------------------------
extern "C" void kernel_launch(void* const* d_in, const int* in_sizes, int n_in,
                              void* d_out, int out_size) {
    const float* q = (const float*)d_in[0];
    const float* k = (const float*)d_in[1];
    const float* v = (const float*)d_in[2];
    const float* lq1 = (const float*)d_in[3];
    const float* lq2 = (const float*)d_in[4];
    const float* lk1 = (const float*)d_in[5];
    const float* lk2 = (const float*)d_in[6];
    const float* gamma = (const float*)d_in[7];
    const float* beta = (const float*)d_in[8];
    float* out = (float*)d_out;

    cudaFuncSetAttribute(attn_kernel, cudaFuncAttributeMaxDynamicSharedMemorySize, SMEM_BYTES);

    dim3 cgrid(NT, NH);
    conv_kernel<<<cgrid, 256>>>(k, v);
    dim3 grid(SEQ / BM, NH);
    attn_kernel<<<grid, 256, SMEM_BYTES>>>(q, out, lq1, lq2, lk1, lk2);
    int total8 = NH * SEQ * HD / 8;
    norm_kernel<<<total8 / 256, 256>>>(out, gamma, beta);
}

// round 12
// speedup vs baseline: 1.0146x; 1.0146x over previous
#include <cuda_runtime.h>
#include <cuda_fp16.h>
#include <cstdint>

#define NH 16
#define SEQ 2048
#define HD 64
#define BM 128
#define BN 64
#define NT (SEQ / BN)    // 32

#define PU 36
#define PF 72

// ---- SMEM layout (bytes) ----
#define TILE_B (64 * 144)                 // 9216
#define BUF_B (3 * TILE_B)                // 27648
#define SK1_B(b) ((b) * BUF_B)
#define SRED_B (2 * BUF_B)                // 55296
#define SLAM_B (SRED_B + 32)
#define SMEM_BYTES (SLAM_B + 32)

// ---- global scratch: per (head, tile) packed fp16 image, 192 rows x 128B ----
#define SCRT_B (192 * 128)                // 24576: [K1 64r | K2 64r | VT 64r]
__device__ uint8_t g_scr[NH * NT * SCRT_B];

__device__ float g_psum[NH * 16];
__device__ float g_psq[NH * 16];
__device__ float g_mean[NH];
__device__ float g_istd[NH];
__device__ int g_cnt[NH];

__device__ __forceinline__ float ex2(float x) {
    float r; asm("ex2.approx.ftz.f32 %0, %1;" : "=f"(r) : "f"(x)); return r;
}
__device__ __forceinline__ uint32_t pack2(float lo, float hi) {
    uint32_t r;
    asm("cvt.rn.f16x2.f32 %0, %1, %2;" : "=r"(r) : "f"(hi), "f"(lo));
    return r;
}
__device__ __forceinline__ uint32_t smem_u32(const void* p) {
    uint32_t a;
    asm("{ .reg .u64 t; cvta.to.shared.u64 t, %1; cvt.u32.u64 %0, t; }" : "=r"(a) : "l"(p));
    return a;
}
__device__ __forceinline__ void mma16(float d[4], const uint32_t a[4], const uint32_t b[2]) {
    asm volatile(
        "mma.sync.aligned.m16n8k16.row.col.f32.f16.f16.f32 "
        "{%0,%1,%2,%3},{%4,%5,%6,%7},{%8,%9},{%0,%1,%2,%3};"
        : "+f"(d[0]), "+f"(d[1]), "+f"(d[2]), "+f"(d[3])
        : "r"(a[0]), "r"(a[1]), "r"(a[2]), "r"(a[3]), "r"(b[0]), "r"(b[1]));
}
__device__ __forceinline__ void ldsm_x4(uint32_t b[4], uint32_t addr) {
    asm volatile("ldmatrix.sync.aligned.m8n8.x4.shared.b16 {%0,%1,%2,%3}, [%4];"
                 : "=r"(b[0]), "=r"(b[1]), "=r"(b[2]), "=r"(b[3]) : "r"(addr));
}
#define CP_ASYNC16(dst, src) \
    asm volatile("cp.async.cg.shared.global [%0], [%1], 16;" :: "r"(dst), "l"(src) : "memory")
#define CP_COMMIT() asm volatile("cp.async.commit_group;" ::: "memory")
#define CP_WAIT0()  asm volatile("cp.async.wait_group 0;" ::: "memory")

// ---------------------------------------------------------------------------
// Prepass (512 threads): convert K halves and V (transposed via smem) to fp16.
// ---------------------------------------------------------------------------
__global__ void __launch_bounds__(512) conv_kernel(const float* __restrict__ k,
                                                   const float* __restrict__ v) {
    __shared__ float sv[64 * 65];
    const int t = blockIdx.x;
    const int h = blockIdx.y;
    const int tid = threadIdx.x;
    const int kbase = t * BN;
    const float* kh = k + (size_t)h * SEQ * 2 * HD;
    const float* vh = v + (size_t)h * SEQ * HD;
    uint8_t* dst = g_scr + (size_t)(h * NT + t) * SCRT_B;

    // K halves: 1024 16B stores, 512 threads -> 2 iterations
#pragma unroll
    for (int i = 0; i < 2; i++) {
        int e = tid + i * 512;          // 0..1023
        int r = e >> 4;                 // 0..63
        int c8 = e & 15;                // 8-col group
        const float* src = kh + (size_t)(kbase + r) * 2 * HD + c8 * 8;
        float4 a = *(const float4*)(src);
        float4 b = *(const float4*)(src + 4);
        int off = ((c8 < 8) ? 0 : 8192) + r * 128 + (c8 & 7) * 16;
        uint4 pk = {pack2(a.x, a.y), pack2(a.z, a.w), pack2(b.x, b.y), pack2(b.z, b.w)};
        *(uint4*)(dst + off) = pk;
    }
    // V: coalesced load into smem (fp32), 1024 float4, 512 threads -> 2 iters
#pragma unroll
    for (int i = 0; i < 2; i++) {
        int e = tid + i * 512;          // 0..1023
        int r = e >> 4;
        int c4 = e & 15;
        float4 val = *(const float4*)(vh + (size_t)(kbase + r) * HD + c4 * 4);
        float* d = sv + r * 65 + c4 * 4;
        d[0] = val.x; d[1] = val.y; d[2] = val.z; d[3] = val.w;
    }
    __syncthreads();
    // transpose write: 512 16B chunks, one per thread
    {
        int e = tid;                    // 0..511
        int d = e >> 3;                 // 0..63
        int k0 = (e & 7) * 8;
        uint4 pk;
        pk.x = pack2(sv[(k0 + 0) * 65 + d], sv[(k0 + 1) * 65 + d]);
        pk.y = pack2(sv[(k0 + 2) * 65 + d], sv[(k0 + 3) * 65 + d]);
        pk.z = pack2(sv[(k0 + 4) * 65 + d], sv[(k0 + 5) * 65 + d]);
        pk.w = pack2(sv[(k0 + 6) * 65 + d], sv[(k0 + 7) * 65 + d]);
        *(uint4*)(dst + 16384 + d * 128 + k0 * 2) = pk;
    }
}

// ---------------------------------------------------------------------------
__global__ void __launch_bounds__(256, 2) attn_kernel(
    const float* __restrict__ q, float* __restrict__ out,
    const float* __restrict__ lq1, const float* __restrict__ lq2,
    const float* __restrict__ lk1, const float* __restrict__ lk2) {
    extern __shared__ char smc[];
    uint32_t* smu = (uint32_t*)smc;
    float* smf = (float*)smc;
    const uint32_t sb = smem_u32(smc);

    const int tid = threadIdx.x;
    const int w = tid >> 5;
    const int lane = tid & 31;
    const int lq = lane >> 2;
    const int lt = lane & 3;
    const int half2w = (w >= 4);
    const int wrow = (w & 3) * 32;
    const int h = blockIdx.y;
    const int qbase = blockIdx.x * BM;

    const float C = 0.18033688011112042f;  // (1/8)*log2(e)

    const float* qh = q + (size_t)h * SEQ * 2 * HD;
    const uint8_t* scr = g_scr + (size_t)h * NT * SCRT_B;

    const uint32_t lmQK = (uint32_t)((lane & 7) * 144 + ((lane >> 3) & 1) * 16 + ((lane >> 4) & 1) * 32);
    const uint32_t lmPV = (uint32_t)((lane & 7) * 144 + ((lane >> 3) & 1) * 16 + ((lane >> 4) & 1) * 1152);

    // ---- warp 0: lambda into smem (read back only AFTER the mainloop) ----
    if (w == 0) {
        float a = lq1[lane] * lk1[lane] + lq1[lane + 32] * lk1[lane + 32];
        float b = lq2[lane] * lk2[lane] + lq2[lane + 32] * lk2[lane + 32];
#pragma unroll
        for (int o = 16; o > 0; o >>= 1) {
            a += __shfl_xor_sync(0xffffffffu, a, o);
            b += __shfl_xor_sync(0xffffffffu, b, o);
        }
        if (lane == 0) smf[SLAM_B >> 2] = __expf(a) - __expf(b) + 0.8f;
    }

    // ---- stage Q (fp16, scaled): Q1 at byte 0, Q2 at byte BUF_B ----
    for (int e = tid; e < BM * 32; e += 256) {
        int c4 = e & 31;
        int r = e >> 5;
        float4 val = *(const float4*)(qh + (size_t)(qbase + r) * 2 * HD + c4 * 4);
        int baseu = ((c4 < 16) ? 0 : BUF_B) >> 2;
        int d0 = (c4 & 15) * 4;
        uint2 pk = {pack2(val.x * C, val.y * C), pack2(val.z * C, val.w * C)};
        *(uint2*)(smu + baseu + r * PU + (d0 >> 1)) = pk;
    }
    __syncthreads();

    // ---- extract Q fragments ----
    uint32_t qa[2][4][4];
    {
        const uint32_t* sq = smu + ((half2w ? BUF_B : 0) >> 2);
#pragma unroll
        for (int m = 0; m < 2; m++)
#pragma unroll
            for (int kg = 0; kg < 4; kg++) {
                int r0 = wrow + m * 16 + lq;
                int c0 = kg * 8 + lt;
                qa[m][kg][0] = sq[r0 * PU + c0];
                qa[m][kg][1] = sq[(r0 + 8) * PU + c0];
                qa[m][kg][2] = sq[r0 * PU + c0 + 4];
                qa[m][kg][3] = sq[(r0 + 8) * PU + c0 + 4];
            }
    }
    __syncthreads();

    // ---- prologue: async-stage tile 0 into buffer 0 ----
#pragma unroll
    for (int i = 0; i < 6; i++) {
        int c = tid + i * 256;
        uint32_t dst = sb + SK1_B(0) + (c >> 3) * 144 + (c & 7) * 16;
        CP_ASYNC16(dst, scr + c * 16);
    }
    CP_COMMIT();

    float o[2][8][4] = {};
    float lrow[4] = {};

    for (int t = 0; t < NT; t++) {
        CP_WAIT0();
        __syncthreads();

        const int buf = t & 1;
        if (t + 1 < NT) {
            const uint8_t* src = scr + (size_t)(t + 1) * SCRT_B;
            const uint32_t db = sb + SK1_B(buf ^ 1);
#pragma unroll
            for (int i = 0; i < 6; i++) {
                int c = tid + i * 256;
                CP_ASYNC16(db + (c >> 3) * 144 + (c & 7) * 16, src + c * 16);
            }
        }
        CP_COMMIT();

        const uint32_t skA = sb + SK1_B(buf) + (half2w ? TILE_B : 0) + lmQK;
        const uint32_t svA = sb + SK1_B(buf) + 2 * TILE_B + lmPV;

        // ---- per k-group: QK (two n-tiles) -> softmax -> P in regs -> PV ----
#pragma unroll
        for (int kg = 0; kg < 4; kg++) {
            uint32_t pa[2][4];
#pragma unroll
            for (int p = 0; p < 2; p++) {
                const int n = kg * 2 + p;
                float s[2][4] = {};
#pragma unroll
                for (int j = 0; j < 2; j++) {
                    uint32_t b4[4];
                    ldsm_x4(b4, skA + n * 1152 + j * 64);
                    mma16(s[0], qa[0][2 * j], b4);
                    mma16(s[1], qa[1][2 * j], b4);
                    mma16(s[0], qa[0][2 * j + 1], b4 + 2);
                    mma16(s[1], qa[1][2 * j + 1], b4 + 2);
                }
#pragma unroll
                for (int m = 0; m < 2; m++) {
                    float p0 = ex2(s[m][0]), p1 = ex2(s[m][1]);
                    float p2 = ex2(s[m][2]), p3 = ex2(s[m][3]);
                    lrow[m * 2 + 0] += p0 + p1;
                    lrow[m * 2 + 1] += p2 + p3;
                    pa[m][p * 2 + 0] = pack2(p0, p1);
                    pa[m][p * 2 + 1] = pack2(p2, p3);
                }
            }
#pragma unroll
            for (int n2 = 0; n2 < 4; n2++) {
                uint32_t b4[4];
                ldsm_x4(b4, svA + n2 * 2304 + kg * 32);
                mma16(o[0][2 * n2], pa[0], b4);
                mma16(o[1][2 * n2], pa[1], b4);
                mma16(o[0][2 * n2 + 1], pa[0], b4 + 2);
                mma16(o[1][2 * n2 + 1], pa[1], b4 + 2);
            }
        }
    }

    // ---- quad-reduce softmax denominators ----
#pragma unroll
    for (int i = 0; i < 4; i++) {
        lrow[i] += __shfl_xor_sync(0xffffffffu, lrow[i], 1);
        lrow[i] += __shfl_xor_sync(0xffffffffu, lrow[i], 2);
    }

    const float lam = smf[SLAM_B >> 2];
    __syncthreads();

    float* exg = smf;
    if (half2w) {
#pragma unroll
        for (int m = 0; m < 2; m++) {
            float s0 = lam / lrow[m * 2 + 0];
            float s1 = lam / lrow[m * 2 + 1];
            int r0 = wrow + m * 16 + lq;
#pragma unroll
            for (int n = 0; n < 8; n++) {
                float* pp = exg + r0 * PF + n * 8 + lt * 2;
                pp[0] = o[m][n][0] * s0;
                pp[1] = o[m][n][1] * s0;
                pp[8 * PF] = o[m][n][2] * s1;
                pp[8 * PF + 1] = o[m][n][3] * s1;
            }
        }
    }
    __syncthreads();

    if (!half2w) {
        float lsum = 0.f, lsq = 0.f;
#pragma unroll
        for (int m = 0; m < 2; m++) {
            float r0s = 1.f / lrow[m * 2 + 0];
            float r1s = 1.f / lrow[m * 2 + 1];
            int r0 = wrow + m * 16 + lq;
            float* orow0 = out + ((size_t)h * SEQ + qbase + r0) * HD;
            float* orow1 = out + ((size_t)h * SEQ + qbase + r0 + 8) * HD;
#pragma unroll
            for (int n = 0; n < 8; n++) {
                const float* pp = exg + r0 * PF + n * 8 + lt * 2;
                float v0 = o[m][n][0] * r0s - pp[0];
                float v1 = o[m][n][1] * r0s - pp[1];
                float v2 = o[m][n][2] * r1s - pp[8 * PF];
                float v3 = o[m][n][3] * r1s - pp[8 * PF + 1];
                int c = n * 8 + lt * 2;
                float2 t0 = {v0, v1};
                float2 t1 = {v2, v3};
                *(float2*)(orow0 + c) = t0;
                *(float2*)(orow1 + c) = t1;
                lsum += v0 + v1 + v2 + v3;
                lsq += v0 * v0 + v1 * v1 + v2 * v2 + v3 * v3;
            }
        }
#pragma unroll
        for (int off = 16; off > 0; off >>= 1) {
            lsum += __shfl_xor_sync(0xffffffffu, lsum, off);
            lsq += __shfl_xor_sync(0xffffffffu, lsq, off);
        }
        if (lane == 0) { smf[(SRED_B >> 2) + w] = lsum; smf[(SRED_B >> 2) + 4 + w] = lsq; }
    }
    __syncthreads();
    if (tid == 0) {
        const float* rd = smf + (SRED_B >> 2);
        g_psum[h * 16 + blockIdx.x] = rd[0] + rd[1] + rd[2] + rd[3];
        g_psq[h * 16 + blockIdx.x] = rd[4] + rd[5] + rd[6] + rd[7];
        __threadfence();
        int c = atomicAdd(&g_cnt[h], 1);
        if (c == 15) {
            float s = 0.f, qq = 0.f;
#pragma unroll
            for (int i = 0; i < 16; i++) { s += g_psum[h * 16 + i]; qq += g_psq[h * 16 + i]; }
            const float inv_n = 1.0f / (float)(SEQ * HD);
            float mean = s * inv_n;
            float var = qq * inv_n - mean * mean;
            g_mean[h] = mean;
            g_istd[h] = rsqrtf(var + 1e-5f);
            g_cnt[h] = 0;
        }
    }
}

// ---------------------------------------------------------------------------
__global__ void norm_kernel(float* __restrict__ out, const float* __restrict__ gamma,
                            const float* __restrict__ beta) {
    int idx = (blockIdx.x * blockDim.x + threadIdx.x) * 4;
    int h = idx >> 17;
    int d = idx & (HD - 1);
    float mean = g_mean[h];
    float is = g_istd[h];
    float4 x = *(float4*)(out + idx);
    float4 g = *(const float4*)(gamma + h * HD + d);
    float4 b = *(const float4*)(beta + h * HD + d);
    x.x = ((x.x - mean) * is * g.x + b.x) * 0.2f;
    x.y = ((x.y - mean) * is * g.y + b.y) * 0.2f;
    x.z = ((x.z - mean) * is * g.z + b.z) * 0.2f;
    x.w = ((x.w - mean) * is * g.w + b.w) * 0.2f;
    *(float4*)(out + idx) = x;
}

// ---------------------------------------------------------------------------
extern "C" void kernel_launch(void* const* d_in, const int* in_sizes, int n_in,
                              void* d_out, int out_size) {
    const float* q = (const float*)d_in[0];
    const float* k = (const float*)d_in[1];
    const float* v = (const float*)d_in[2];
    const float* lq1 = (const float*)d_in[3];
    const float* lq2 = (const float*)d_in[4];
    const float* lk1 = (const float*)d_in[5];
    const float* lk2 = (const float*)d_in[6];
    const float* gamma = (const float*)d_in[7];
    const float* beta = (const float*)d_in[8];
    float* out = (float*)d_out;

    cudaFuncSetAttribute(attn_kernel, cudaFuncAttributeMaxDynamicSharedMemorySize, SMEM_BYTES);

    dim3 cgrid(NT, NH);
    conv_kernel<<<cgrid, 512>>>(k, v);
    dim3 grid(SEQ / BM, NH);
    attn_kernel<<<grid, 256, SMEM_BYTES>>>(q, out, lq1, lq2, lk1, lk2);
    int total4 = NH * SEQ * HD / 4;
    norm_kernel<<<total4 / 256, 256>>>(out, gamma, beta);
}